// round 15
// baseline (speedup 1.0000x reference)
#include <cuda_runtime.h>
#include <cuda_bf16.h>
#include <cstdint>
#include <math.h>

// Problem constants
#define BB   4
#define LLEN 1024
#define DD   1024
#define HH   16
#define DHH  64
#define FF   4096

typedef __nv_bfloat16 bf16;

// ---------------- scratch (static device globals; no runtime allocation) ----
__device__ float g_proj[BB * LLEN * DD];
__device__ float g_t1  [BB * LLEN * DD];
__device__ float g_t2  [BB * LLEN * DD];
// bf16 hi/lo split buffers
__device__ bf16 g_ah[(size_t)BB * LLEN * DD];       // generic A split
__device__ bf16 g_al[(size_t)BB * LLEN * DD];
__device__ bf16 g_bh[(size_t)DD * FF];              // weight^T split (concat ok)
__device__ bf16 g_bl[(size_t)DD * FF];
__device__ bf16 g_hh[(size_t)BB * LLEN * FF];       // FFN hidden split
__device__ bf16 g_hl[(size_t)BB * LLEN * FF];
// attention operands
__device__ bf16 g_qkvh[(size_t)BB * LLEN * 3 * DD]; // packed QKV (self) / KV (cross)
__device__ bf16 g_qkvl[(size_t)BB * LLEN * 3 * DD];
__device__ bf16 g_qh[BB * LLEN * DD];               // cross-attn Q
__device__ bf16 g_ql[BB * LLEN * DD];
__device__ bf16 g_vth[BB * DD * LLEN];              // V^T: [B][H][dh][L]
__device__ bf16 g_vtl[BB * DD * LLEN];

// =====================================================================
// low-level helpers (base-ISA: ldmatrix / mma.sync / cp.async)
// =====================================================================
__device__ __forceinline__ uint32_t smem_u32(const void* p) {
    uint32_t a;
    asm("{ .reg .u64 t; cvta.to.shared.u64 t, %1; cvt.u32.u64 %0, t; }"
        : "=r"(a) : "l"(p));
    return a;
}
__device__ __forceinline__ void cp16(uint32_t dst, const void* src) {
    asm volatile("cp.async.cg.shared.global [%0], [%1], 16;"
                 :: "r"(dst), "l"(src) : "memory");
}
__device__ __forceinline__ void cp_commit() {
    asm volatile("cp.async.commit_group;" ::: "memory");
}
template<int N>
__device__ __forceinline__ void cp_wait() {
    asm volatile("cp.async.wait_group %0;" :: "n"(N) : "memory");
}
__device__ __forceinline__ void ldsm4(uint32_t* r, uint32_t a) {
    asm volatile("ldmatrix.sync.aligned.m8n8.x4.shared.b16 {%0,%1,%2,%3}, [%4];"
                 : "=r"(r[0]), "=r"(r[1]), "=r"(r[2]), "=r"(r[3]) : "r"(a));
}
__device__ __forceinline__ void ldsm2(uint32_t* r, uint32_t a) {
    asm volatile("ldmatrix.sync.aligned.m8n8.x2.shared.b16 {%0,%1}, [%2];"
                 : "=r"(r[0]), "=r"(r[1]) : "r"(a));
}
__device__ __forceinline__ void mma16816(float* c, const uint32_t* a,
                                         const uint32_t* b) {
    asm volatile(
        "mma.sync.aligned.m16n8k16.row.col.f32.bf16.bf16.f32 "
        "{%0,%1,%2,%3}, {%4,%5,%6,%7}, {%8,%9}, {%0,%1,%2,%3};"
        : "+f"(c[0]), "+f"(c[1]), "+f"(c[2]), "+f"(c[3])
        : "r"(a[0]), "r"(a[1]), "r"(a[2]), "r"(a[3]), "r"(b[0]), "r"(b[1]));
}
__device__ __forceinline__ uint32_t packbf2(float a, float b) {
    __nv_bfloat162 t = __floats2bfloat162_rn(a, b);
    return *(uint32_t*)&t;
}
__device__ __forceinline__ void split1(float v, bf16& h, bf16& l) {
    h = __float2bfloat16(v);
    l = __float2bfloat16(v - __bfloat162float(h));
}

#define PITCH 40                       // dense GEMM smem pitch (bf16)
#define TILEB (128 * PITCH * 2)
#define STAGEB (4 * TILEB)
#define SMEMB (2 * STAGEB)             // 81920

// =====================================================================
// Dense HMMA bf16-split GEMM: acc = Ah@Bh^T + Ah@Bl^T + Al@Bh^T
// Tile 128x128, 512 threads (4x4 warps, each 32x32) -> 4 warps/SMSP for
// latency hiding (profile showed tensor=52%, issue=15.6% at 8 warps).
// ACT: 0 none, 1 +bias, 2 +bias+gelu.  OUT: 0 fp32 C, 1 bf16 hi/lo (Ch,Cl)
// =====================================================================
template<int ACT, int OUT>
__global__ __launch_bounds__(512)
void mma_gemm_kernel(const bf16* __restrict__ Ah, const bf16* __restrict__ Al,
                     const bf16* __restrict__ Bh, const bf16* __restrict__ Bl,
                     float* __restrict__ C,
                     bf16* __restrict__ Ch, bf16* __restrict__ Cl,
                     const float* __restrict__ bias,
                     int M, int N, int K)
{
    extern __shared__ char smem[];
    uint32_t sb = smem_u32(smem);
    int tid  = threadIdx.x;
    int wid  = tid >> 5;
    int lane = tid & 31;
    int wm = wid & 3;          // 4 warps in M (32 rows each)
    int wn = wid >> 2;         // 4 warps in N (32 cols each)

    int m0 = blockIdx.x * 128;
    int n0 = blockIdx.y * 128;
    const bf16* pAh = Ah + (long long)m0 * K;
    const bf16* pAl = Al + (long long)m0 * K;
    const bf16* pBh = Bh + (long long)n0 * K;
    const bf16* pBl = Bl + (long long)n0 * K;

    float acc[2][4][4];
#pragma unroll
    for (int i = 0; i < 2; i++)
#pragma unroll
        for (int j = 0; j < 4; j++)
#pragma unroll
            for (int q = 0; q < 4; q++) acc[i][j][q] = 0.f;

    // 512 slots per tile (128 rows x 4 x 16B groups); 1 slot/thread/tile
    int rs = tid >> 2, cs = tid & 3;
    uint32_t so = rs * (PITCH * 2) + cs * 16;

    auto load_chunk = [&](int c, int s) {
        int kt = c * 32;
        uint32_t base = sb + s * STAGEB;
        long long g = (long long)rs * K + kt + cs * 8;
        cp16(base + 0 * TILEB + so, pAh + g);
        cp16(base + 1 * TILEB + so, pAl + g);
        cp16(base + 2 * TILEB + so, pBh + g);
        cp16(base + 3 * TILEB + so, pBl + g);
    };

    int nCh = K / 32;
    load_chunk(0, 0);
    cp_commit();

    for (int c = 0; c < nCh; c++) {
        int cur = c & 1;
        if (c + 1 < nCh) {
            load_chunk(c + 1, cur ^ 1);
            cp_commit();
            cp_wait<1>();
        } else {
            cp_wait<0>();
        }
        __syncthreads();

        uint32_t tAh = sb + cur * STAGEB;
        uint32_t tAl = tAh + TILEB;
        uint32_t tBh = tAl + TILEB;
        uint32_t tBl = tBh + TILEB;

#pragma unroll
        for (int ks = 0; ks < 2; ks++) {
            uint32_t bh[4][2], bl[4][2];
            int brow = wn * 32 + (lane & 7);
            int bcol = ks * 16 + ((lane >> 3) & 1) * 8;
#pragma unroll
            for (int nt = 0; nt < 4; nt++) {
                uint32_t off = (uint32_t)(brow + nt * 8) * (PITCH * 2) + bcol * 2;
                ldsm2(bh[nt], tBh + off);
                ldsm2(bl[nt], tBl + off);
            }
            int arow = wm * 32 + (lane & 15);
            int acol = ks * 16 + (lane >> 4) * 8;
#pragma unroll
            for (int mt = 0; mt < 2; mt++) {
                uint32_t ah[4], al[4];
                uint32_t off = (uint32_t)(arow + mt * 16) * (PITCH * 2) + acol * 2;
                ldsm4(ah, tAh + off);
                ldsm4(al, tAl + off);
                // pass-major: 4 independent MMAs per pass
#pragma unroll
                for (int nt = 0; nt < 4; nt++)
                    mma16816(acc[mt][nt], ah, bh[nt]);
#pragma unroll
                for (int nt = 0; nt < 4; nt++)
                    mma16816(acc[mt][nt], ah, bl[nt]);
#pragma unroll
                for (int nt = 0; nt < 4; nt++)
                    mma16816(acc[mt][nt], al, bh[nt]);
            }
        }
        __syncthreads();
    }

#pragma unroll
    for (int mt = 0; mt < 2; mt++) {
#pragma unroll
        for (int nt = 0; nt < 4; nt++) {
            int r0 = m0 + wm * 32 + mt * 16 + (lane >> 2);
            int cc = n0 + wn * 32 + nt * 8 + (lane & 3) * 2;
#pragma unroll
            for (int half = 0; half < 2; half++) {
                int rr = r0 + half * 8;
                float v0 = acc[mt][nt][half * 2 + 0];
                float v1 = acc[mt][nt][half * 2 + 1];
                if (ACT >= 1) { v0 += bias[cc]; v1 += bias[cc + 1]; }
                if (ACT == 2) {
                    float x3 = v0 * v0 * v0;
                    v0 = 0.5f * v0 * (1.f + tanhf(0.7978845608028654f *
                                                  (v0 + 0.044715f * x3)));
                    x3 = v1 * v1 * v1;
                    v1 = 0.5f * v1 * (1.f + tanhf(0.7978845608028654f *
                                                  (v1 + 0.044715f * x3)));
                }
                long long off = (long long)rr * N + cc;
                if (OUT == 0) {
                    *(float2*)&C[off] = make_float2(v0, v1);
                } else {
                    bf16 h0, l0, h1, l1;
                    split1(v0, h0, l0);
                    split1(v1, h1, l1);
                    __nv_bfloat162 hp; hp.x = h0; hp.y = h1;
                    __nv_bfloat162 lp; lp.x = l0; lp.y = l1;
                    *(uint32_t*)&Ch[off] = *(uint32_t*)&hp;
                    *(uint32_t*)&Cl[off] = *(uint32_t*)&lp;
                }
            }
        }
    }
}

// =====================================================================
// Fused flash attention (unchanged R14 champion, pass-major MMAs).
// =====================================================================
#define FPITCH 72
#define FROWB (FPITCH * 2)             // 144 B smem row
#define FQ_TILE (128 * FROWB)          // 18432
#define FK_TILE (64 * FROWB)           // 9216
#define FSTAGE  (4 * FK_TILE)          // 36864
#define FSM_ST  (2 * FQ_TILE)          // 36864
#define FSM_TOTAL (FSM_ST + 2 * FSTAGE) // 110592

template<bool CAUSAL>
__global__ __launch_bounds__(256, 1)
void flash_kernel(const bf16* __restrict__ Qh_, const bf16* __restrict__ Ql_,
                  int qld,
                  const bf16* __restrict__ Kh_, const bf16* __restrict__ Kl_,
                  int kld,
                  const bf16* __restrict__ Vth_, const bf16* __restrict__ Vtl_,
                  bf16* __restrict__ Oh_, bf16* __restrict__ Ol_)
{
    extern __shared__ char smem[];
    uint32_t sb = smem_u32(smem);
    int tid  = threadIdx.x;
    int wid  = tid >> 5;
    int lane = tid & 31;

    int m0 = blockIdx.x * 128;
    int z = blockIdx.z;
    int b = z / HH, h = z % HH;
    long long qBase = (long long)b * LLEN * qld + h * DHH + (long long)m0 * qld;
    long long kBase = (long long)b * LLEN * kld + h * DHH;
    long long vBase = ((long long)b * DD + h * DHH) * LLEN;

#pragma unroll
    for (int i = 0; i < 4; i++) {
        int g = tid + i * 256;
        int r = g >> 3, c = g & 7;
        uint32_t so = (uint32_t)r * FROWB + c * 16;
        long long gq = (long long)r * qld + c * 8;
        cp16(sb + so, Qh_ + qBase + gq);
        cp16(sb + FQ_TILE + so, Ql_ + qBase + gq);
    }
    auto load_stage = [&](int step, int s) {
        int kv0 = step * 64;
        uint32_t base = sb + FSM_ST + s * FSTAGE;
#pragma unroll
        for (int i = 0; i < 2; i++) {
            int g = tid + i * 256;
            int r = g >> 3, c = g & 7;
            uint32_t so = (uint32_t)r * FROWB + c * 16;
            long long gk = (long long)(kv0 + r) * kld + c * 8;
            long long gv = (long long)r * LLEN + kv0 + c * 8;
            cp16(base + 0 * FK_TILE + so, Kh_ + kBase + gk);
            cp16(base + 1 * FK_TILE + so, Kl_ + kBase + gk);
            cp16(base + 2 * FK_TILE + so, Vth_ + vBase + gv);
            cp16(base + 3 * FK_TILE + so, Vtl_ + vBase + gv);
        }
    };

    int nSteps = CAUSAL ? (m0 / 64 + 2) : (LLEN / 64);
    load_stage(0, 0);
    cp_commit();

    float O[8][4];
#pragma unroll
    for (int i = 0; i < 8; i++)
#pragma unroll
        for (int j = 0; j < 4; j++) O[i][j] = 0.f;
    float mrow0 = -INFINITY, mrow1 = -INFINITY;
    float lrow0 = 0.f, lrow1 = 0.f;

    uint32_t qh[4][4], ql[4][4];

    for (int st = 0; st < nSteps; st++) {
        int cur = st & 1;
        if (st + 1 < nSteps) {
            load_stage(st + 1, cur ^ 1);
            cp_commit();
            cp_wait<1>();
        } else {
            cp_wait<0>();
        }
        __syncthreads();

        if (st == 0) {
            int arow = wid * 16 + (lane & 15);
#pragma unroll
            for (int c = 0; c < 4; c++) {
                int acol = c * 16 + (lane >> 4) * 8;
                uint32_t off = (uint32_t)arow * FROWB + acol * 2;
                ldsm4(qh[c], sb + off);
                ldsm4(ql[c], sb + FQ_TILE + off);
            }
        }

        uint32_t tKh = sb + FSM_ST + cur * FSTAGE;
        uint32_t tKl = tKh + FK_TILE;
        uint32_t tVh = tKl + FK_TILE;
        uint32_t tVl = tVh + FK_TILE;

        float S[8][4];
#pragma unroll
        for (int i = 0; i < 8; i++)
#pragma unroll
            for (int j = 0; j < 4; j++) S[i][j] = 0.f;

#pragma unroll
        for (int c = 0; c < 4; c++) {
            uint32_t bh[8][2], bl[8][2];
            int brow = lane & 7;
            int bcol = c * 16 + ((lane >> 3) & 1) * 8;
#pragma unroll
            for (int nt = 0; nt < 8; nt++) {
                uint32_t off = (uint32_t)(brow + nt * 8) * FROWB + bcol * 2;
                ldsm2(bh[nt], tKh + off);
                ldsm2(bl[nt], tKl + off);
            }
#pragma unroll
            for (int nt = 0; nt < 8; nt++)
                mma16816(S[nt], qh[c], bh[nt]);
#pragma unroll
            for (int nt = 0; nt < 8; nt++)
                mma16816(S[nt], qh[c], bl[nt]);
#pragma unroll
            for (int nt = 0; nt < 8; nt++)
                mma16816(S[nt], ql[c], bh[nt]);
        }

        int kv0 = st * 64;
#pragma unroll
        for (int nt = 0; nt < 8; nt++) {
#pragma unroll
            for (int j = 0; j < 4; j++) S[nt][j] *= 0.125f;
        }
        if (CAUSAL && kv0 + 63 > m0) {
            int row0 = m0 + wid * 16 + (lane >> 2);
#pragma unroll
            for (int nt = 0; nt < 8; nt++) {
                int col0 = kv0 + nt * 8 + (lane & 3) * 2;
                if (col0 > row0)     S[nt][0] = -1e30f;
                if (col0 + 1 > row0) S[nt][1] = -1e30f;
                if (col0 > row0 + 8)     S[nt][2] = -1e30f;
                if (col0 + 1 > row0 + 8) S[nt][3] = -1e30f;
            }
        }

        float mx0 = -1e30f, mx1 = -1e30f;
#pragma unroll
        for (int nt = 0; nt < 8; nt++) {
            mx0 = fmaxf(mx0, fmaxf(S[nt][0], S[nt][1]));
            mx1 = fmaxf(mx1, fmaxf(S[nt][2], S[nt][3]));
        }
        mx0 = fmaxf(mx0, __shfl_xor_sync(0xffffffffu, mx0, 1));
        mx0 = fmaxf(mx0, __shfl_xor_sync(0xffffffffu, mx0, 2));
        mx1 = fmaxf(mx1, __shfl_xor_sync(0xffffffffu, mx1, 1));
        mx1 = fmaxf(mx1, __shfl_xor_sync(0xffffffffu, mx1, 2));

        float mn0 = fmaxf(mrow0, mx0);
        float mn1 = fmaxf(mrow1, mx1);
        float f0 = __expf(mrow0 - mn0);
        float f1 = __expf(mrow1 - mn1);
        mrow0 = mn0; mrow1 = mn1;

        float sum0 = 0.f, sum1 = 0.f;
        uint32_t ph[8][2], pl[8][2];
#pragma unroll
        for (int nt = 0; nt < 8; nt++) {
            float p0 = __expf(S[nt][0] - mn0);
            float p1 = __expf(S[nt][1] - mn0);
            float p2 = __expf(S[nt][2] - mn1);
            float p3 = __expf(S[nt][3] - mn1);
            sum0 += p0 + p1;
            sum1 += p2 + p3;
            bf16 h0 = __float2bfloat16(p0), h1 = __float2bfloat16(p1);
            bf16 h2 = __float2bfloat16(p2), h3 = __float2bfloat16(p3);
            __nv_bfloat162 hp0; hp0.x = h0; hp0.y = h1;
            __nv_bfloat162 hp1; hp1.x = h2; hp1.y = h3;
            ph[nt][0] = *(uint32_t*)&hp0;
            ph[nt][1] = *(uint32_t*)&hp1;
            pl[nt][0] = packbf2(p0 - __bfloat162float(h0),
                                p1 - __bfloat162float(h1));
            pl[nt][1] = packbf2(p2 - __bfloat162float(h2),
                                p3 - __bfloat162float(h3));
        }
        sum0 += __shfl_xor_sync(0xffffffffu, sum0, 1);
        sum0 += __shfl_xor_sync(0xffffffffu, sum0, 2);
        sum1 += __shfl_xor_sync(0xffffffffu, sum1, 1);
        sum1 += __shfl_xor_sync(0xffffffffu, sum1, 2);
        lrow0 = lrow0 * f0 + sum0;
        lrow1 = lrow1 * f1 + sum1;

#pragma unroll
        for (int nt = 0; nt < 8; nt++) {
            O[nt][0] *= f0; O[nt][1] *= f0;
            O[nt][2] *= f1; O[nt][3] *= f1;
        }

#pragma unroll
        for (int c = 0; c < 4; c++) {
            uint32_t a_h[4] = { ph[2*c][0], ph[2*c][1], ph[2*c+1][0], ph[2*c+1][1] };
            uint32_t a_l[4] = { pl[2*c][0], pl[2*c][1], pl[2*c+1][0], pl[2*c+1][1] };
            uint32_t vh[8][2], vl[8][2];
            int brow = lane & 7;
            int bcol = c * 16 + ((lane >> 3) & 1) * 8;
#pragma unroll
            for (int nt = 0; nt < 8; nt++) {
                uint32_t off = (uint32_t)(brow + nt * 8) * FROWB + bcol * 2;
                ldsm2(vh[nt], tVh + off);
                ldsm2(vl[nt], tVl + off);
            }
#pragma unroll
            for (int nt = 0; nt < 8; nt++)
                mma16816(O[nt], a_h, vh[nt]);
#pragma unroll
            for (int nt = 0; nt < 8; nt++)
                mma16816(O[nt], a_h, vl[nt]);
#pragma unroll
            for (int nt = 0; nt < 8; nt++)
                mma16816(O[nt], a_l, vh[nt]);
        }
        __syncthreads();
    }

    float inv0 = 1.f / lrow0;
    float inv1 = 1.f / lrow1;
    long long base = (long long)b * LLEN * DD +
                     (long long)(m0 + wid * 16) * DD + h * DHH;
    int r = lane >> 2;
    int c0 = (lane & 3) * 2;
#pragma unroll
    for (int nt = 0; nt < 8; nt++) {
        {
            float o0 = O[nt][0] * inv0, o1 = O[nt][1] * inv0;
            bf16 h0, l0, h1, l1;
            split1(o0, h0, l0); split1(o1, h1, l1);
            __nv_bfloat162 hp; hp.x = h0; hp.y = h1;
            __nv_bfloat162 lp; lp.x = l0; lp.y = l1;
            long long off = base + (long long)r * DD + nt * 8 + c0;
            *(uint32_t*)&Oh_[off] = *(uint32_t*)&hp;
            *(uint32_t*)&Ol_[off] = *(uint32_t*)&lp;
        }
        {
            float o0 = O[nt][2] * inv1, o1 = O[nt][3] * inv1;
            bf16 h0, l0, h1, l1;
            split1(o0, h0, l0); split1(o1, h1, l1);
            __nv_bfloat162 hp; hp.x = h0; hp.y = h1;
            __nv_bfloat162 lp; lp.x = l0; lp.y = l1;
            long long off = base + (long long)(r + 8) * DD + nt * 8 + c0;
            *(uint32_t*)&Oh_[off] = *(uint32_t*)&hp;
            *(uint32_t*)&Ol_[off] = *(uint32_t*)&lp;
        }
    }
}

// =====================================================================
// fp32 -> bf16 hi/lo split (elementwise) — raw inputs only
// =====================================================================
__global__ void split_kernel(const float* __restrict__ x,
                             bf16* __restrict__ h, bf16* __restrict__ l,
                             long long n)
{
    long long i = ((long long)blockIdx.x * blockDim.x + threadIdx.x) * 4;
    if (i >= n) return;
    float4 v = *(const float4*)(x + i);
    bf16 h0, l0, h1, l1, h2, l2, h3, l3;
    split1(v.x, h0, l0); split1(v.y, h1, l1);
    split1(v.z, h2, l2); split1(v.w, h3, l3);
    __nv_bfloat162 hp0 = {h0, h1}, hp1 = {h2, h3};
    __nv_bfloat162 lp0 = {l0, l1}, lp1 = {l2, l3};
    uint2 hv, lv;
    hv.x = *(uint32_t*)&hp0; hv.y = *(uint32_t*)&hp1;
    lv.x = *(uint32_t*)&lp0; lv.y = *(uint32_t*)&lp1;
    *(uint2*)(h + i) = hv;
    *(uint2*)(l + i) = lv;
}

// =====================================================================
// W [K,N] fp32 -> W^T [N,K] bf16 hi/lo (into caller-offset dest). block (32,8)
// =====================================================================
__global__ void splitT_kernel(const float* __restrict__ W,
                              bf16* __restrict__ Th, bf16* __restrict__ Tl,
                              int K, int N)
{
    __shared__ float t[32][33];
    int bx = blockIdx.x * 32;
    int by = blockIdx.y * 32;
    int tx = threadIdx.x, ty = threadIdx.y;
#pragma unroll
    for (int i = 0; i < 4; i++)
        t[ty + i * 8][tx] = W[(long long)(by + ty + i * 8) * N + bx + tx];
    __syncthreads();
#pragma unroll
    for (int i = 0; i < 4; i++) {
        float v = t[tx][ty + i * 8];
        bf16 hh, ll;
        split1(v, hh, ll);
        long long o = (long long)(bx + ty + i * 8) * K + by + tx;
        Th[o] = hh;
        Tl[o] = ll;
    }
}

// =====================================================================
// bf16 hi/lo V [B,L,ld-packed] -> Vt [B,D,L] hi/lo transpose.
// =====================================================================
__global__ void transposeBf_kernel(const bf16* __restrict__ Sh,
                                   const bf16* __restrict__ Sl, int ld,
                                   bf16* __restrict__ Th, bf16* __restrict__ Tl)
{
    __shared__ bf16 th[32][33];
    __shared__ bf16 tl[32][33];
    int d0 = blockIdx.x * 32;
    int k0 = blockIdx.y * 32;
    long long sbase = (long long)blockIdx.z * LLEN * ld;
    long long ob = (long long)blockIdx.z * DD * LLEN;
    int tx = threadIdx.x, ty = threadIdx.y;
#pragma unroll
    for (int i = 0; i < 4; i++) {
        long long s = sbase + (long long)(k0 + ty + i * 8) * ld + d0 + tx;
        th[ty + i * 8][tx] = Sh[s];
        tl[ty + i * 8][tx] = Sl[s];
    }
    __syncthreads();
#pragma unroll
    for (int i = 0; i < 4; i++) {
        long long o = ob + (long long)(d0 + ty + i * 8) * LLEN + k0 + tx;
        Th[o] = th[tx][ty + i * 8];
        Tl[o] = tl[tx][ty + i * 8];
    }
}

// ---------------- residual add + LayerNorm (optional fused split out) -------
template<bool SPLIT>
__global__ void add_ln_kernel(const float* __restrict__ x,
                              const float* __restrict__ res,
                              const float* __restrict__ w,
                              const float* __restrict__ bp,
                              float* __restrict__ out,
                              bf16* __restrict__ oh, bf16* __restrict__ ol)
{
    long long row = blockIdx.x;
    const float* xr = x   + row * DD;
    const float* rr = res + row * DD;
    float*       orow = out + row * DD;
    int t = threadIdx.x;

    __shared__ float red[256];

    float v[4];
    float s = 0.f;
#pragma unroll
    for (int i = 0; i < 4; i++) {
        int idx = t + i * 256;
        v[i] = xr[idx] + rr[idx];
        s += v[i];
    }
    red[t] = s; __syncthreads();
    for (int k = 128; k > 0; k >>= 1) { if (t < k) red[t] += red[t + k]; __syncthreads(); }
    float mu = red[0] * (1.f / DD); __syncthreads();

    float vs = 0.f;
#pragma unroll
    for (int i = 0; i < 4; i++) { float d = v[i] - mu; vs += d * d; }
    red[t] = vs; __syncthreads();
    for (int k = 128; k > 0; k >>= 1) { if (t < k) red[t] += red[t + k]; __syncthreads(); }
    float rstd = rsqrtf(red[0] * (1.f / DD) + 1e-5f);

#pragma unroll
    for (int i = 0; i < 4; i++) {
        int idx = t + i * 256;
        float o = (v[i] - mu) * rstd * w[idx] + bp[idx];
        orow[idx] = o;
        if (SPLIT) {
            bf16 hh, ll;
            split1(o, hh, ll);
            oh[row * DD + idx] = hh;
            ol[row * DD + idx] = ll;
        }
    }
}

// ---------------- host orchestration ----------------------------------------
static bf16 *s_ah, *s_al, *s_bh, *s_bl, *s_hh, *s_hl;
static bf16 *s_qkvh, *s_qkvl, *s_qh, *s_ql, *s_vth, *s_vtl;

static inline void split_launch(const float* x, bf16* h, bf16* l, long long n)
{
    split_kernel<<<(unsigned)((n / 4 + 255) / 256), 256>>>(x, h, l, n);
}
static inline void splitT_launch(const float* w, int K, int N, int rowOff)
{
    splitT_kernel<<<dim3(N / 32, K / 32), dim3(32, 8)>>>(
        w, s_bh + (long long)rowOff * K, s_bl + (long long)rowOff * K, K, N);
}

extern "C" void kernel_launch(void* const* d_in, const int* in_sizes, int n_in,
                              void* d_out, int out_size)
{
    (void)in_sizes; (void)n_in; (void)out_size;

    const float* tgt    = (const float*)d_in[0];
    const float* memv   = (const float*)d_in[1];
    const float* sa_wq  = (const float*)d_in[4];
    const float* sa_wk  = (const float*)d_in[5];
    const float* sa_wv  = (const float*)d_in[6];
    const float* sa_wo  = (const float*)d_in[7];
    const float* ca_wq  = (const float*)d_in[8];
    const float* ca_wk  = (const float*)d_in[9];
    const float* ca_wv  = (const float*)d_in[10];
    const float* ca_wo  = (const float*)d_in[11];
    const float* ffn_w1 = (const float*)d_in[12];
    const float* ffn_b1 = (const float*)d_in[13];
    const float* ffn_w2 = (const float*)d_in[14];
    const float* ffn_b2 = (const float*)d_in[15];
    const float* ln1_w  = (const float*)d_in[16];
    const float* ln1_b  = (const float*)d_in[17];
    const float* ln2_w  = (const float*)d_in[18];
    const float* ln2_b  = (const float*)d_in[19];
    const float* ln3_w  = (const float*)d_in[20];
    const float* ln3_b  = (const float*)d_in[21];

    float *proj, *t1, *t2;
    cudaGetSymbolAddress((void**)&proj, g_proj);
    cudaGetSymbolAddress((void**)&t1,   g_t1);
    cudaGetSymbolAddress((void**)&t2,   g_t2);
    cudaGetSymbolAddress((void**)&s_ah, g_ah);
    cudaGetSymbolAddress((void**)&s_al, g_al);
    cudaGetSymbolAddress((void**)&s_bh, g_bh);
    cudaGetSymbolAddress((void**)&s_bl, g_bl);
    cudaGetSymbolAddress((void**)&s_hh, g_hh);
    cudaGetSymbolAddress((void**)&s_hl, g_hl);
    cudaGetSymbolAddress((void**)&s_qkvh, g_qkvh);
    cudaGetSymbolAddress((void**)&s_qkvl, g_qkvl);
    cudaGetSymbolAddress((void**)&s_qh, g_qh);
    cudaGetSymbolAddress((void**)&s_ql, g_ql);
    cudaGetSymbolAddress((void**)&s_vth, g_vth);
    cudaGetSymbolAddress((void**)&s_vtl, g_vtl);

    cudaFuncSetAttribute(mma_gemm_kernel<0,0>, cudaFuncAttributeMaxDynamicSharedMemorySize, SMEMB);
    cudaFuncSetAttribute(mma_gemm_kernel<0,1>, cudaFuncAttributeMaxDynamicSharedMemorySize, SMEMB);
    cudaFuncSetAttribute(mma_gemm_kernel<1,0>, cudaFuncAttributeMaxDynamicSharedMemorySize, SMEMB);
    cudaFuncSetAttribute(mma_gemm_kernel<2,1>, cudaFuncAttributeMaxDynamicSharedMemorySize, SMEMB);
    cudaFuncSetAttribute(flash_kernel<true>,  cudaFuncAttributeMaxDynamicSharedMemorySize, FSM_TOTAL);
    cudaFuncSetAttribute(flash_kernel<false>, cudaFuncAttributeMaxDynamicSharedMemorySize, FSM_TOTAL);

    const int M = BB * LLEN;
    dim3 gFl(LLEN / 128, 1, BB * HH);
    dim3 gT(DD / 32, LLEN / 32, BB);
    dim3 gD(M / 128, DD / 128);         // N=1024 GEMM grid
    dim3 gQKV(M / 128, 3 * DD / 128);   // N=3072 merged QKV grid
    dim3 gKV(M / 128, 2 * DD / 128);    // N=2048 merged KV grid
    dim3 gF1(M / 128, FF / 128);        // FFN w1 grid

    // =========== Self-attention ===========
    split_launch(tgt, s_ah, s_al, (long long)M * DD);
    splitT_launch(sa_wq, DD, DD, 0);
    splitT_launch(sa_wk, DD, DD, DD);
    splitT_launch(sa_wv, DD, DD, 2 * DD);
    mma_gemm_kernel<0,1><<<gQKV, 512, SMEMB>>>(s_ah, s_al, s_bh, s_bl,
        nullptr, s_qkvh, s_qkvl, nullptr, M, 3 * DD, DD);
    transposeBf_kernel<<<gT, dim3(32, 8)>>>(s_qkvh + 2 * DD, s_qkvl + 2 * DD,
                                            3 * DD, s_vth, s_vtl);

    flash_kernel<true><<<gFl, 256, FSM_TOTAL>>>(
        s_qkvh, s_qkvl, 3 * DD,
        s_qkvh + DD, s_qkvl + DD, 3 * DD,
        s_vth, s_vtl, s_ah, s_al);

    splitT_launch(sa_wo, DD, DD, 0);
    mma_gemm_kernel<0,0><<<gD, 512, SMEMB>>>(s_ah, s_al, s_bh, s_bl,
        proj, nullptr, nullptr, nullptr, M, DD, DD);
    add_ln_kernel<true><<<M, 256>>>(proj, tgt, ln1_w, ln1_b, t1, s_ah, s_al);

    // =========== Cross-attention ===========
    splitT_launch(ca_wq, DD, DD, 0);
    mma_gemm_kernel<0,1><<<gD, 512, SMEMB>>>(s_ah, s_al, s_bh, s_bl,
        nullptr, s_qh, s_ql, nullptr, M, DD, DD);
    split_launch(memv, s_ah, s_al, (long long)M * DD);
    splitT_launch(ca_wk, DD, DD, 0);
    splitT_launch(ca_wv, DD, DD, DD);
    mma_gemm_kernel<0,1><<<gKV, 512, SMEMB>>>(s_ah, s_al, s_bh, s_bl,
        nullptr, s_qkvh, s_qkvl, nullptr, M, 2 * DD, DD);
    transposeBf_kernel<<<gT, dim3(32, 8)>>>(s_qkvh + DD, s_qkvl + DD,
                                            2 * DD, s_vth, s_vtl);

    flash_kernel<false><<<gFl, 256, FSM_TOTAL>>>(
        s_qh, s_ql, DD,
        s_qkvh, s_qkvl, 2 * DD,
        s_vth, s_vtl, s_ah, s_al);

    splitT_launch(ca_wo, DD, DD, 0);
    mma_gemm_kernel<0,0><<<gD, 512, SMEMB>>>(s_ah, s_al, s_bh, s_bl,
        proj, nullptr, nullptr, nullptr, M, DD, DD);
    add_ln_kernel<true><<<M, 256>>>(proj, t1, ln2_w, ln2_b, t2, s_ah, s_al);

    // =========== FFN ===========
    splitT_launch(ffn_w1, DD, FF, 0);
    mma_gemm_kernel<2,1><<<gF1, 512, SMEMB>>>(s_ah, s_al, s_bh, s_bl,
        nullptr, s_hh, s_hl, ffn_b1, M, FF, DD);
    splitT_launch(ffn_w2, FF, DD, 0);
    mma_gemm_kernel<1,0><<<gD, 512, SMEMB>>>(s_hh, s_hl, s_bh, s_bl,
        proj, nullptr, nullptr, ffn_b2, M, DD, FF);
    add_ln_kernel<false><<<M, 256>>>(proj, t2, ln3_w, ln3_b, (float*)d_out,
                                     nullptr, nullptr);
}

// round 16
// speedup vs baseline: 1.0717x; 1.0717x over previous
#include <cuda_runtime.h>
#include <cuda_bf16.h>
#include <cstdint>
#include <math.h>

// Problem constants
#define BB   4
#define LLEN 1024
#define DD   1024
#define HH   16
#define DHH  64
#define FF   4096

typedef __nv_bfloat16 bf16;

// ---------------- scratch (static device globals; no runtime allocation) ----
__device__ float g_proj[BB * LLEN * DD];
__device__ float g_t1  [BB * LLEN * DD];
__device__ float g_t2  [BB * LLEN * DD];
// bf16 hi/lo split buffers
__device__ bf16 g_ah[(size_t)BB * LLEN * DD];       // generic A split
__device__ bf16 g_al[(size_t)BB * LLEN * DD];
__device__ bf16 g_mh[(size_t)BB * LLEN * DD];       // memv split
__device__ bf16 g_ml[(size_t)BB * LLEN * DD];
__device__ bf16 g_bh[(size_t)DD * FF];              // weight^T split (concat ok)
__device__ bf16 g_bl[(size_t)DD * FF];
__device__ bf16 g_hh[(size_t)BB * LLEN * FF];       // FFN hidden split
__device__ bf16 g_hl[(size_t)BB * LLEN * FF];
// attention operands
__device__ bf16 g_qkvh[(size_t)BB * LLEN * 3 * DD]; // packed Q|K|V
__device__ bf16 g_qkvl[(size_t)BB * LLEN * 3 * DD];
__device__ bf16 g_vth[BB * DD * LLEN];              // V^T: [B][H][dh][L]
__device__ bf16 g_vtl[BB * DD * LLEN];

// =====================================================================
// low-level helpers (base-ISA: ldmatrix / mma.sync / cp.async)
// =====================================================================
__device__ __forceinline__ uint32_t smem_u32(const void* p) {
    uint32_t a;
    asm("{ .reg .u64 t; cvta.to.shared.u64 t, %1; cvt.u32.u64 %0, t; }"
        : "=r"(a) : "l"(p));
    return a;
}
__device__ __forceinline__ void cp16(uint32_t dst, const void* src) {
    asm volatile("cp.async.cg.shared.global [%0], [%1], 16;"
                 :: "r"(dst), "l"(src) : "memory");
}
__device__ __forceinline__ void cp_commit() {
    asm volatile("cp.async.commit_group;" ::: "memory");
}
template<int N>
__device__ __forceinline__ void cp_wait() {
    asm volatile("cp.async.wait_group %0;" :: "n"(N) : "memory");
}
__device__ __forceinline__ void ldsm4(uint32_t* r, uint32_t a) {
    asm volatile("ldmatrix.sync.aligned.m8n8.x4.shared.b16 {%0,%1,%2,%3}, [%4];"
                 : "=r"(r[0]), "=r"(r[1]), "=r"(r[2]), "=r"(r[3]) : "r"(a));
}
__device__ __forceinline__ void ldsm2(uint32_t* r, uint32_t a) {
    asm volatile("ldmatrix.sync.aligned.m8n8.x2.shared.b16 {%0,%1}, [%2];"
                 : "=r"(r[0]), "=r"(r[1]) : "r"(a));
}
__device__ __forceinline__ void mma16816(float* c, const uint32_t* a,
                                         const uint32_t* b) {
    asm volatile(
        "mma.sync.aligned.m16n8k16.row.col.f32.bf16.bf16.f32 "
        "{%0,%1,%2,%3}, {%4,%5,%6,%7}, {%8,%9}, {%0,%1,%2,%3};"
        : "+f"(c[0]), "+f"(c[1]), "+f"(c[2]), "+f"(c[3])
        : "r"(a[0]), "r"(a[1]), "r"(a[2]), "r"(a[3]), "r"(b[0]), "r"(b[1]));
}
__device__ __forceinline__ uint32_t packbf2(float a, float b) {
    __nv_bfloat162 t = __floats2bfloat162_rn(a, b);
    return *(uint32_t*)&t;
}
__device__ __forceinline__ void split1(float v, bf16& h, bf16& l) {
    h = __float2bfloat16(v);
    l = __float2bfloat16(v - __bfloat162float(h));
}

#define PITCH 40                       // dense GEMM smem pitch (bf16)
#define TILEB (128 * PITCH * 2)
#define STAGEB (4 * TILEB)
#define SMEMB (2 * STAGEB)             // 81920 (champion config)

// =====================================================================
// Dense HMMA bf16-split GEMM: acc = Ah@Bh^T + Ah@Bl^T + Al@Bh^T
// R14 champion mainloop (256 thr, 64x32 warp tiles, 2-stage, pass-major).
// Dual-A: blocks with n0 >= nSplit read A2 (merged cross Q|KV GEMM).
// ACT: 0 none, 1 +bias, 2 +bias+gelu.  OUT: 0 fp32 C, 1 bf16 hi/lo (Ch,Cl)
// =====================================================================
template<int ACT, int OUT>
__global__ __launch_bounds__(256)
void mma_gemm_kernel(const bf16* __restrict__ A1h, const bf16* __restrict__ A1l,
                     const bf16* __restrict__ A2h, const bf16* __restrict__ A2l,
                     int nSplit,
                     const bf16* __restrict__ Bh, const bf16* __restrict__ Bl,
                     float* __restrict__ C,
                     bf16* __restrict__ Ch, bf16* __restrict__ Cl,
                     const float* __restrict__ bias,
                     int M, int N, int K)
{
    extern __shared__ char smem[];
    uint32_t sb = smem_u32(smem);
    int tid  = threadIdx.x;
    int wid  = tid >> 5;
    int lane = tid & 31;
    int wm = wid & 1;
    int wn = wid >> 1;

    int m0 = blockIdx.x * 128;
    int n0 = blockIdx.y * 128;
    const bf16* Ah = (n0 >= nSplit) ? A2h : A1h;
    const bf16* Al = (n0 >= nSplit) ? A2l : A1l;
    const bf16* pAh = Ah + (long long)m0 * K;
    const bf16* pAl = Al + (long long)m0 * K;
    const bf16* pBh = Bh + (long long)n0 * K;
    const bf16* pBl = Bl + (long long)n0 * K;

    float acc[4][4][4];
#pragma unroll
    for (int i = 0; i < 4; i++)
#pragma unroll
        for (int j = 0; j < 4; j++)
#pragma unroll
            for (int q = 0; q < 4; q++) acc[i][j][q] = 0.f;

    int r0s = (tid + 0)   >> 2, c0s = (tid + 0)   & 3;
    int r1s = (tid + 256) >> 2, c1s = (tid + 256) & 3;
    uint32_t so0 = r0s * (PITCH * 2) + c0s * 16;
    uint32_t so1 = r1s * (PITCH * 2) + c1s * 16;

    auto load_chunk = [&](int c, int s) {
        int kt = c * 32;
        uint32_t base = sb + s * STAGEB;
        long long g0 = (long long)r0s * K + kt + c0s * 8;
        long long g1 = (long long)r1s * K + kt + c1s * 8;
        cp16(base + 0 * TILEB + so0, pAh + g0);
        cp16(base + 0 * TILEB + so1, pAh + g1);
        cp16(base + 1 * TILEB + so0, pAl + g0);
        cp16(base + 1 * TILEB + so1, pAl + g1);
        cp16(base + 2 * TILEB + so0, pBh + g0);
        cp16(base + 2 * TILEB + so1, pBh + g1);
        cp16(base + 3 * TILEB + so0, pBl + g0);
        cp16(base + 3 * TILEB + so1, pBl + g1);
    };

    int nCh = K / 32;
    load_chunk(0, 0);
    cp_commit();

    for (int c = 0; c < nCh; c++) {
        int cur = c & 1;
        if (c + 1 < nCh) {
            load_chunk(c + 1, cur ^ 1);
            cp_commit();
            cp_wait<1>();
        } else {
            cp_wait<0>();
        }
        __syncthreads();

        uint32_t tAh = sb + cur * STAGEB;
        uint32_t tAl = tAh + TILEB;
        uint32_t tBh = tAl + TILEB;
        uint32_t tBl = tBh + TILEB;

#pragma unroll
        for (int ks = 0; ks < 2; ks++) {
            uint32_t bh[4][2], bl[4][2];
            int brow = wn * 32 + (lane & 7);
            int bcol = ks * 16 + ((lane >> 3) & 1) * 8;
#pragma unroll
            for (int nt = 0; nt < 4; nt++) {
                uint32_t off = (uint32_t)(brow + nt * 8) * (PITCH * 2) + bcol * 2;
                ldsm2(bh[nt], tBh + off);
                ldsm2(bl[nt], tBl + off);
            }
            int arow = wm * 64 + (lane & 15);
            int acol = ks * 16 + (lane >> 4) * 8;
#pragma unroll
            for (int mt = 0; mt < 4; mt++) {
                uint32_t ah[4], al[4];
                uint32_t off = (uint32_t)(arow + mt * 16) * (PITCH * 2) + acol * 2;
                ldsm4(ah, tAh + off);
                ldsm4(al, tAl + off);
                // pass-major: 4 independent MMAs per pass
#pragma unroll
                for (int nt = 0; nt < 4; nt++)
                    mma16816(acc[mt][nt], ah, bh[nt]);
#pragma unroll
                for (int nt = 0; nt < 4; nt++)
                    mma16816(acc[mt][nt], ah, bl[nt]);
#pragma unroll
                for (int nt = 0; nt < 4; nt++)
                    mma16816(acc[mt][nt], al, bh[nt]);
            }
        }
        __syncthreads();
    }

#pragma unroll
    for (int mt = 0; mt < 4; mt++) {
#pragma unroll
        for (int nt = 0; nt < 4; nt++) {
            int r0 = m0 + wm * 64 + mt * 16 + (lane >> 2);
            int cc = n0 + wn * 32 + nt * 8 + (lane & 3) * 2;
#pragma unroll
            for (int half = 0; half < 2; half++) {
                int rr = r0 + half * 8;
                float v0 = acc[mt][nt][half * 2 + 0];
                float v1 = acc[mt][nt][half * 2 + 1];
                if (ACT >= 1) { v0 += bias[cc]; v1 += bias[cc + 1]; }
                if (ACT == 2) {
                    float x3 = v0 * v0 * v0;
                    v0 = 0.5f * v0 * (1.f + tanhf(0.7978845608028654f *
                                                  (v0 + 0.044715f * x3)));
                    x3 = v1 * v1 * v1;
                    v1 = 0.5f * v1 * (1.f + tanhf(0.7978845608028654f *
                                                  (v1 + 0.044715f * x3)));
                }
                long long off = (long long)rr * N + cc;
                if (OUT == 0) {
                    *(float2*)&C[off] = make_float2(v0, v1);
                } else {
                    bf16 h0, l0, h1, l1;
                    split1(v0, h0, l0);
                    split1(v1, h1, l1);
                    __nv_bfloat162 hp; hp.x = h0; hp.y = h1;
                    __nv_bfloat162 lp; lp.x = l0; lp.y = l1;
                    *(uint32_t*)&Ch[off] = *(uint32_t*)&hp;
                    *(uint32_t*)&Cl[off] = *(uint32_t*)&lp;
                }
            }
        }
    }
}

// =====================================================================
// Fused flash attention (R14 champion, pass-major MMAs).
// =====================================================================
#define FPITCH 72
#define FROWB (FPITCH * 2)             // 144 B smem row
#define FQ_TILE (128 * FROWB)          // 18432
#define FK_TILE (64 * FROWB)           // 9216
#define FSTAGE  (4 * FK_TILE)          // 36864
#define FSM_ST  (2 * FQ_TILE)          // 36864
#define FSM_TOTAL (FSM_ST + 2 * FSTAGE) // 110592

template<bool CAUSAL>
__global__ __launch_bounds__(256, 1)
void flash_kernel(const bf16* __restrict__ Qh_, const bf16* __restrict__ Ql_,
                  int qld,
                  const bf16* __restrict__ Kh_, const bf16* __restrict__ Kl_,
                  int kld,
                  const bf16* __restrict__ Vth_, const bf16* __restrict__ Vtl_,
                  bf16* __restrict__ Oh_, bf16* __restrict__ Ol_)
{
    extern __shared__ char smem[];
    uint32_t sb = smem_u32(smem);
    int tid  = threadIdx.x;
    int wid  = tid >> 5;
    int lane = tid & 31;

    int m0 = blockIdx.x * 128;
    int z = blockIdx.z;
    int b = z / HH, h = z % HH;
    long long qBase = (long long)b * LLEN * qld + h * DHH + (long long)m0 * qld;
    long long kBase = (long long)b * LLEN * kld + h * DHH;
    long long vBase = ((long long)b * DD + h * DHH) * LLEN;

#pragma unroll
    for (int i = 0; i < 4; i++) {
        int g = tid + i * 256;
        int r = g >> 3, c = g & 7;
        uint32_t so = (uint32_t)r * FROWB + c * 16;
        long long gq = (long long)r * qld + c * 8;
        cp16(sb + so, Qh_ + qBase + gq);
        cp16(sb + FQ_TILE + so, Ql_ + qBase + gq);
    }
    auto load_stage = [&](int step, int s) {
        int kv0 = step * 64;
        uint32_t base = sb + FSM_ST + s * FSTAGE;
#pragma unroll
        for (int i = 0; i < 2; i++) {
            int g = tid + i * 256;
            int r = g >> 3, c = g & 7;
            uint32_t so = (uint32_t)r * FROWB + c * 16;
            long long gk = (long long)(kv0 + r) * kld + c * 8;
            long long gv = (long long)r * LLEN + kv0 + c * 8;
            cp16(base + 0 * FK_TILE + so, Kh_ + kBase + gk);
            cp16(base + 1 * FK_TILE + so, Kl_ + kBase + gk);
            cp16(base + 2 * FK_TILE + so, Vth_ + vBase + gv);
            cp16(base + 3 * FK_TILE + so, Vtl_ + vBase + gv);
        }
    };

    int nSteps = CAUSAL ? (m0 / 64 + 2) : (LLEN / 64);
    load_stage(0, 0);
    cp_commit();

    float O[8][4];
#pragma unroll
    for (int i = 0; i < 8; i++)
#pragma unroll
        for (int j = 0; j < 4; j++) O[i][j] = 0.f;
    float mrow0 = -INFINITY, mrow1 = -INFINITY;
    float lrow0 = 0.f, lrow1 = 0.f;

    uint32_t qh[4][4], ql[4][4];

    for (int st = 0; st < nSteps; st++) {
        int cur = st & 1;
        if (st + 1 < nSteps) {
            load_stage(st + 1, cur ^ 1);
            cp_commit();
            cp_wait<1>();
        } else {
            cp_wait<0>();
        }
        __syncthreads();

        if (st == 0) {
            int arow = wid * 16 + (lane & 15);
#pragma unroll
            for (int c = 0; c < 4; c++) {
                int acol = c * 16 + (lane >> 4) * 8;
                uint32_t off = (uint32_t)arow * FROWB + acol * 2;
                ldsm4(qh[c], sb + off);
                ldsm4(ql[c], sb + FQ_TILE + off);
            }
        }

        uint32_t tKh = sb + FSM_ST + cur * FSTAGE;
        uint32_t tKl = tKh + FK_TILE;
        uint32_t tVh = tKl + FK_TILE;
        uint32_t tVl = tVh + FK_TILE;

        float S[8][4];
#pragma unroll
        for (int i = 0; i < 8; i++)
#pragma unroll
            for (int j = 0; j < 4; j++) S[i][j] = 0.f;

#pragma unroll
        for (int c = 0; c < 4; c++) {
            uint32_t bh[8][2], bl[8][2];
            int brow = lane & 7;
            int bcol = c * 16 + ((lane >> 3) & 1) * 8;
#pragma unroll
            for (int nt = 0; nt < 8; nt++) {
                uint32_t off = (uint32_t)(brow + nt * 8) * FROWB + bcol * 2;
                ldsm2(bh[nt], tKh + off);
                ldsm2(bl[nt], tKl + off);
            }
#pragma unroll
            for (int nt = 0; nt < 8; nt++)
                mma16816(S[nt], qh[c], bh[nt]);
#pragma unroll
            for (int nt = 0; nt < 8; nt++)
                mma16816(S[nt], qh[c], bl[nt]);
#pragma unroll
            for (int nt = 0; nt < 8; nt++)
                mma16816(S[nt], ql[c], bh[nt]);
        }

        int kv0 = st * 64;
#pragma unroll
        for (int nt = 0; nt < 8; nt++) {
#pragma unroll
            for (int j = 0; j < 4; j++) S[nt][j] *= 0.125f;
        }
        if (CAUSAL && kv0 + 63 > m0) {
            int row0 = m0 + wid * 16 + (lane >> 2);
#pragma unroll
            for (int nt = 0; nt < 8; nt++) {
                int col0 = kv0 + nt * 8 + (lane & 3) * 2;
                if (col0 > row0)     S[nt][0] = -1e30f;
                if (col0 + 1 > row0) S[nt][1] = -1e30f;
                if (col0 > row0 + 8)     S[nt][2] = -1e30f;
                if (col0 + 1 > row0 + 8) S[nt][3] = -1e30f;
            }
        }

        float mx0 = -1e30f, mx1 = -1e30f;
#pragma unroll
        for (int nt = 0; nt < 8; nt++) {
            mx0 = fmaxf(mx0, fmaxf(S[nt][0], S[nt][1]));
            mx1 = fmaxf(mx1, fmaxf(S[nt][2], S[nt][3]));
        }
        mx0 = fmaxf(mx0, __shfl_xor_sync(0xffffffffu, mx0, 1));
        mx0 = fmaxf(mx0, __shfl_xor_sync(0xffffffffu, mx0, 2));
        mx1 = fmaxf(mx1, __shfl_xor_sync(0xffffffffu, mx1, 1));
        mx1 = fmaxf(mx1, __shfl_xor_sync(0xffffffffu, mx1, 2));

        float mn0 = fmaxf(mrow0, mx0);
        float mn1 = fmaxf(mrow1, mx1);
        float f0 = __expf(mrow0 - mn0);
        float f1 = __expf(mrow1 - mn1);
        mrow0 = mn0; mrow1 = mn1;

        float sum0 = 0.f, sum1 = 0.f;
        uint32_t ph[8][2], pl[8][2];
#pragma unroll
        for (int nt = 0; nt < 8; nt++) {
            float p0 = __expf(S[nt][0] - mn0);
            float p1 = __expf(S[nt][1] - mn0);
            float p2 = __expf(S[nt][2] - mn1);
            float p3 = __expf(S[nt][3] - mn1);
            sum0 += p0 + p1;
            sum1 += p2 + p3;
            bf16 h0 = __float2bfloat16(p0), h1 = __float2bfloat16(p1);
            bf16 h2 = __float2bfloat16(p2), h3 = __float2bfloat16(p3);
            __nv_bfloat162 hp0; hp0.x = h0; hp0.y = h1;
            __nv_bfloat162 hp1; hp1.x = h2; hp1.y = h3;
            ph[nt][0] = *(uint32_t*)&hp0;
            ph[nt][1] = *(uint32_t*)&hp1;
            pl[nt][0] = packbf2(p0 - __bfloat162float(h0),
                                p1 - __bfloat162float(h1));
            pl[nt][1] = packbf2(p2 - __bfloat162float(h2),
                                p3 - __bfloat162float(h3));
        }
        sum0 += __shfl_xor_sync(0xffffffffu, sum0, 1);
        sum0 += __shfl_xor_sync(0xffffffffu, sum0, 2);
        sum1 += __shfl_xor_sync(0xffffffffu, sum1, 1);
        sum1 += __shfl_xor_sync(0xffffffffu, sum1, 2);
        lrow0 = lrow0 * f0 + sum0;
        lrow1 = lrow1 * f1 + sum1;

#pragma unroll
        for (int nt = 0; nt < 8; nt++) {
            O[nt][0] *= f0; O[nt][1] *= f0;
            O[nt][2] *= f1; O[nt][3] *= f1;
        }

#pragma unroll
        for (int c = 0; c < 4; c++) {
            uint32_t a_h[4] = { ph[2*c][0], ph[2*c][1], ph[2*c+1][0], ph[2*c+1][1] };
            uint32_t a_l[4] = { pl[2*c][0], pl[2*c][1], pl[2*c+1][0], pl[2*c+1][1] };
            uint32_t vh[8][2], vl[8][2];
            int brow = lane & 7;
            int bcol = c * 16 + ((lane >> 3) & 1) * 8;
#pragma unroll
            for (int nt = 0; nt < 8; nt++) {
                uint32_t off = (uint32_t)(brow + nt * 8) * FROWB + bcol * 2;
                ldsm2(vh[nt], tVh + off);
                ldsm2(vl[nt], tVl + off);
            }
#pragma unroll
            for (int nt = 0; nt < 8; nt++)
                mma16816(O[nt], a_h, vh[nt]);
#pragma unroll
            for (int nt = 0; nt < 8; nt++)
                mma16816(O[nt], a_h, vl[nt]);
#pragma unroll
            for (int nt = 0; nt < 8; nt++)
                mma16816(O[nt], a_l, vh[nt]);
        }
        __syncthreads();
    }

    float inv0 = 1.f / lrow0;
    float inv1 = 1.f / lrow1;
    long long base = (long long)b * LLEN * DD +
                     (long long)(m0 + wid * 16) * DD + h * DHH;
    int r = lane >> 2;
    int c0 = (lane & 3) * 2;
#pragma unroll
    for (int nt = 0; nt < 8; nt++) {
        {
            float o0 = O[nt][0] * inv0, o1 = O[nt][1] * inv0;
            bf16 h0, l0, h1, l1;
            split1(o0, h0, l0); split1(o1, h1, l1);
            __nv_bfloat162 hp; hp.x = h0; hp.y = h1;
            __nv_bfloat162 lp; lp.x = l0; lp.y = l1;
            long long off = base + (long long)r * DD + nt * 8 + c0;
            *(uint32_t*)&Oh_[off] = *(uint32_t*)&hp;
            *(uint32_t*)&Ol_[off] = *(uint32_t*)&lp;
        }
        {
            float o0 = O[nt][2] * inv1, o1 = O[nt][3] * inv1;
            bf16 h0, l0, h1, l1;
            split1(o0, h0, l0); split1(o1, h1, l1);
            __nv_bfloat162 hp; hp.x = h0; hp.y = h1;
            __nv_bfloat162 lp; lp.x = l0; lp.y = l1;
            long long off = base + (long long)(r + 8) * DD + nt * 8 + c0;
            *(uint32_t*)&Oh_[off] = *(uint32_t*)&hp;
            *(uint32_t*)&Ol_[off] = *(uint32_t*)&lp;
        }
    }
}

// =====================================================================
// fp32 -> bf16 hi/lo split (elementwise) — raw inputs only
// =====================================================================
__global__ void split_kernel(const float* __restrict__ x,
                             bf16* __restrict__ h, bf16* __restrict__ l,
                             long long n)
{
    long long i = ((long long)blockIdx.x * blockDim.x + threadIdx.x) * 4;
    if (i >= n) return;
    float4 v = *(const float4*)(x + i);
    bf16 h0, l0, h1, l1, h2, l2, h3, l3;
    split1(v.x, h0, l0); split1(v.y, h1, l1);
    split1(v.z, h2, l2); split1(v.w, h3, l3);
    __nv_bfloat162 hp0 = {h0, h1}, hp1 = {h2, h3};
    __nv_bfloat162 lp0 = {l0, l1}, lp1 = {l2, l3};
    uint2 hv, lv;
    hv.x = *(uint32_t*)&hp0; hv.y = *(uint32_t*)&hp1;
    lv.x = *(uint32_t*)&lp0; lv.y = *(uint32_t*)&lp1;
    *(uint2*)(h + i) = hv;
    *(uint2*)(l + i) = lv;
}

// =====================================================================
// W [K,N] fp32 -> W^T [N,K] bf16 hi/lo (into caller-offset dest). block (32,8)
// =====================================================================
__global__ void splitT_kernel(const float* __restrict__ W,
                              bf16* __restrict__ Th, bf16* __restrict__ Tl,
                              int K, int N)
{
    __shared__ float t[32][33];
    int bx = blockIdx.x * 32;
    int by = blockIdx.y * 32;
    int tx = threadIdx.x, ty = threadIdx.y;
#pragma unroll
    for (int i = 0; i < 4; i++)
        t[ty + i * 8][tx] = W[(long long)(by + ty + i * 8) * N + bx + tx];
    __syncthreads();
#pragma unroll
    for (int i = 0; i < 4; i++) {
        float v = t[tx][ty + i * 8];
        bf16 hh, ll;
        split1(v, hh, ll);
        long long o = (long long)(bx + ty + i * 8) * K + by + tx;
        Th[o] = hh;
        Tl[o] = ll;
    }
}

// =====================================================================
// bf16 hi/lo V [B,L,ld-packed] -> Vt [B,D,L] hi/lo transpose.
// =====================================================================
__global__ void transposeBf_kernel(const bf16* __restrict__ Sh,
                                   const bf16* __restrict__ Sl, int ld,
                                   bf16* __restrict__ Th, bf16* __restrict__ Tl)
{
    __shared__ bf16 th[32][33];
    __shared__ bf16 tl[32][33];
    int d0 = blockIdx.x * 32;
    int k0 = blockIdx.y * 32;
    long long sbase = (long long)blockIdx.z * LLEN * ld;
    long long ob = (long long)blockIdx.z * DD * LLEN;
    int tx = threadIdx.x, ty = threadIdx.y;
#pragma unroll
    for (int i = 0; i < 4; i++) {
        long long s = sbase + (long long)(k0 + ty + i * 8) * ld + d0 + tx;
        th[ty + i * 8][tx] = Sh[s];
        tl[ty + i * 8][tx] = Sl[s];
    }
    __syncthreads();
#pragma unroll
    for (int i = 0; i < 4; i++) {
        long long o = ob + (long long)(d0 + ty + i * 8) * LLEN + k0 + tx;
        Th[o] = th[tx][ty + i * 8];
        Tl[o] = tl[tx][ty + i * 8];
    }
}

// ---------------- residual add + LayerNorm (optional fused split out) -------
template<bool SPLIT>
__global__ void add_ln_kernel(const float* __restrict__ x,
                              const float* __restrict__ res,
                              const float* __restrict__ w,
                              const float* __restrict__ bp,
                              float* __restrict__ out,
                              bf16* __restrict__ oh, bf16* __restrict__ ol)
{
    long long row = blockIdx.x;
    const float* xr = x   + row * DD;
    const float* rr = res + row * DD;
    float*       orow = out + row * DD;
    int t = threadIdx.x;

    __shared__ float red[256];

    float v[4];
    float s = 0.f;
#pragma unroll
    for (int i = 0; i < 4; i++) {
        int idx = t + i * 256;
        v[i] = xr[idx] + rr[idx];
        s += v[i];
    }
    red[t] = s; __syncthreads();
    for (int k = 128; k > 0; k >>= 1) { if (t < k) red[t] += red[t + k]; __syncthreads(); }
    float mu = red[0] * (1.f / DD); __syncthreads();

    float vs = 0.f;
#pragma unroll
    for (int i = 0; i < 4; i++) { float d = v[i] - mu; vs += d * d; }
    red[t] = vs; __syncthreads();
    for (int k = 128; k > 0; k >>= 1) { if (t < k) red[t] += red[t + k]; __syncthreads(); }
    float rstd = rsqrtf(red[0] * (1.f / DD) + 1e-5f);

#pragma unroll
    for (int i = 0; i < 4; i++) {
        int idx = t + i * 256;
        float o = (v[i] - mu) * rstd * w[idx] + bp[idx];
        orow[idx] = o;
        if (SPLIT) {
            bf16 hh, ll;
            split1(o, hh, ll);
            oh[row * DD + idx] = hh;
            ol[row * DD + idx] = ll;
        }
    }
}

// ---------------- host orchestration ----------------------------------------
static bf16 *s_ah, *s_al, *s_mh, *s_ml, *s_bh, *s_bl, *s_hh, *s_hl;
static bf16 *s_qkvh, *s_qkvl, *s_vth, *s_vtl;

static inline void split_launch(const float* x, bf16* h, bf16* l, long long n)
{
    split_kernel<<<(unsigned)((n / 4 + 255) / 256), 256>>>(x, h, l, n);
}
static inline void splitT_launch(const float* w, int K, int N, int rowOff)
{
    splitT_kernel<<<dim3(N / 32, K / 32), dim3(32, 8)>>>(
        w, s_bh + (long long)rowOff * K, s_bl + (long long)rowOff * K, K, N);
}

extern "C" void kernel_launch(void* const* d_in, const int* in_sizes, int n_in,
                              void* d_out, int out_size)
{
    (void)in_sizes; (void)n_in; (void)out_size;

    const float* tgt    = (const float*)d_in[0];
    const float* memv   = (const float*)d_in[1];
    const float* sa_wq  = (const float*)d_in[4];
    const float* sa_wk  = (const float*)d_in[5];
    const float* sa_wv  = (const float*)d_in[6];
    const float* sa_wo  = (const float*)d_in[7];
    const float* ca_wq  = (const float*)d_in[8];
    const float* ca_wk  = (const float*)d_in[9];
    const float* ca_wv  = (const float*)d_in[10];
    const float* ca_wo  = (const float*)d_in[11];
    const float* ffn_w1 = (const float*)d_in[12];
    const float* ffn_b1 = (const float*)d_in[13];
    const float* ffn_w2 = (const float*)d_in[14];
    const float* ffn_b2 = (const float*)d_in[15];
    const float* ln1_w  = (const float*)d_in[16];
    const float* ln1_b  = (const float*)d_in[17];
    const float* ln2_w  = (const float*)d_in[18];
    const float* ln2_b  = (const float*)d_in[19];
    const float* ln3_w  = (const float*)d_in[20];
    const float* ln3_b  = (const float*)d_in[21];

    float *proj, *t1, *t2;
    cudaGetSymbolAddress((void**)&proj, g_proj);
    cudaGetSymbolAddress((void**)&t1,   g_t1);
    cudaGetSymbolAddress((void**)&t2,   g_t2);
    cudaGetSymbolAddress((void**)&s_ah, g_ah);
    cudaGetSymbolAddress((void**)&s_al, g_al);
    cudaGetSymbolAddress((void**)&s_mh, g_mh);
    cudaGetSymbolAddress((void**)&s_ml, g_ml);
    cudaGetSymbolAddress((void**)&s_bh, g_bh);
    cudaGetSymbolAddress((void**)&s_bl, g_bl);
    cudaGetSymbolAddress((void**)&s_hh, g_hh);
    cudaGetSymbolAddress((void**)&s_hl, g_hl);
    cudaGetSymbolAddress((void**)&s_qkvh, g_qkvh);
    cudaGetSymbolAddress((void**)&s_qkvl, g_qkvl);
    cudaGetSymbolAddress((void**)&s_vth, g_vth);
    cudaGetSymbolAddress((void**)&s_vtl, g_vtl);

    cudaFuncSetAttribute(mma_gemm_kernel<0,0>, cudaFuncAttributeMaxDynamicSharedMemorySize, SMEMB);
    cudaFuncSetAttribute(mma_gemm_kernel<0,1>, cudaFuncAttributeMaxDynamicSharedMemorySize, SMEMB);
    cudaFuncSetAttribute(mma_gemm_kernel<1,0>, cudaFuncAttributeMaxDynamicSharedMemorySize, SMEMB);
    cudaFuncSetAttribute(mma_gemm_kernel<2,1>, cudaFuncAttributeMaxDynamicSharedMemorySize, SMEMB);
    cudaFuncSetAttribute(flash_kernel<true>,  cudaFuncAttributeMaxDynamicSharedMemorySize, FSM_TOTAL);
    cudaFuncSetAttribute(flash_kernel<false>, cudaFuncAttributeMaxDynamicSharedMemorySize, FSM_TOTAL);

    const int M = BB * LLEN;
    dim3 gFl(LLEN / 128, 1, BB * HH);
    dim3 gT(DD / 32, LLEN / 32, BB);
    dim3 gD(M / 128, DD / 128);         // N=1024 GEMM grid
    dim3 gQKV(M / 128, 3 * DD / 128);   // N=3072 merged QKV grid
    dim3 gF1(M / 128, FF / 128);        // FFN w1 grid

    // =========== Self-attention ===========
    split_launch(tgt,  s_ah, s_al, (long long)M * DD);
    split_launch(memv, s_mh, s_ml, (long long)M * DD);   // early; used in cross
    splitT_launch(sa_wq, DD, DD, 0);
    splitT_launch(sa_wk, DD, DD, DD);
    splitT_launch(sa_wv, DD, DD, 2 * DD);
    mma_gemm_kernel<0,1><<<gQKV, 256, SMEMB>>>(
        s_ah, s_al, s_ah, s_al, 3 * DD,
        s_bh, s_bl, nullptr, s_qkvh, s_qkvl, nullptr, M, 3 * DD, DD);
    transposeBf_kernel<<<gT, dim3(32, 8)>>>(s_qkvh + 2 * DD, s_qkvl + 2 * DD,
                                            3 * DD, s_vth, s_vtl);

    flash_kernel<true><<<gFl, 256, FSM_TOTAL>>>(
        s_qkvh, s_qkvl, 3 * DD,
        s_qkvh + DD, s_qkvl + DD, 3 * DD,
        s_vth, s_vtl, s_ah, s_al);

    splitT_launch(sa_wo, DD, DD, 0);
    mma_gemm_kernel<0,0><<<gD, 256, SMEMB>>>(
        s_ah, s_al, s_ah, s_al, DD,
        s_bh, s_bl, proj, nullptr, nullptr, nullptr, M, DD, DD);
    add_ln_kernel<true><<<M, 256>>>(proj, tgt, ln1_w, ln1_b, t1, s_ah, s_al);

    // =========== Cross-attention ===========
    // merged Q|K|V: blocks n0 < 1024 read A = t1-split, else A = memv-split
    splitT_launch(ca_wq, DD, DD, 0);
    splitT_launch(ca_wk, DD, DD, DD);
    splitT_launch(ca_wv, DD, DD, 2 * DD);
    mma_gemm_kernel<0,1><<<gQKV, 256, SMEMB>>>(
        s_ah, s_al, s_mh, s_ml, DD,
        s_bh, s_bl, nullptr, s_qkvh, s_qkvl, nullptr, M, 3 * DD, DD);
    transposeBf_kernel<<<gT, dim3(32, 8)>>>(s_qkvh + 2 * DD, s_qkvl + 2 * DD,
                                            3 * DD, s_vth, s_vtl);

    flash_kernel<false><<<gFl, 256, FSM_TOTAL>>>(
        s_qkvh, s_qkvl, 3 * DD,
        s_qkvh + DD, s_qkvl + DD, 3 * DD,
        s_vth, s_vtl, s_ah, s_al);

    splitT_launch(ca_wo, DD, DD, 0);
    mma_gemm_kernel<0,0><<<gD, 256, SMEMB>>>(
        s_ah, s_al, s_ah, s_al, DD,
        s_bh, s_bl, proj, nullptr, nullptr, nullptr, M, DD, DD);
    add_ln_kernel<true><<<M, 256>>>(proj, t1, ln2_w, ln2_b, t2, s_ah, s_al);

    // =========== FFN ===========
    splitT_launch(ffn_w1, DD, FF, 0);
    mma_gemm_kernel<2,1><<<gF1, 256, SMEMB>>>(
        s_ah, s_al, s_ah, s_al, FF,
        s_bh, s_bl, nullptr, s_hh, s_hl, ffn_b1, M, FF, DD);
    splitT_launch(ffn_w2, FF, DD, 0);
    mma_gemm_kernel<1,0><<<gD, 256, SMEMB>>>(
        s_hh, s_hl, s_hh, s_hl, DD,
        s_bh, s_bl, proj, nullptr, nullptr, ffn_b2, M, DD, FF);
    add_ln_kernel<false><<<M, 256>>>(proj, t2, ln3_w, ln3_b, (float*)d_out,
                                     nullptr, nullptr);
}